// round 9
// baseline (speedup 1.0000x reference)
#include <cuda_runtime.h>
#include <cuda_bf16.h>
#include <cstdint>

// Problem constants
#define BB 64
#define SS 2048
#define II 64
#define HH 128

// Scratch (allocation-free rule: __device__ globals)
__device__ float g_wx[BB * SS * HH];  // wx0 = x @ w0

// ---------------- f32x2 helpers ----------------
__device__ __forceinline__ unsigned long long pk2(float lo, float hi) {
    unsigned long long r;
    asm("mov.b64 %0, {%1,%2};" : "=l"(r) : "f"(lo), "f"(hi));
    return r;
}
__device__ __forceinline__ unsigned long long ffma2(unsigned long long a,
                                                    unsigned long long b,
                                                    unsigned long long c) {
    unsigned long long d;
    asm("fma.rn.f32x2 %0, %1, %2, %3;" : "=l"(d) : "l"(a), "l"(b), "l"(c));
    return d;
}
__device__ __forceinline__ unsigned long long addx2(unsigned long long a,
                                                    unsigned long long b) {
    unsigned long long d;
    asm("add.rn.f32x2 %0, %1, %2;" : "=l"(d) : "l"(a), "l"(b));
    return d;
}
__device__ __forceinline__ float2 up2(unsigned long long v) {
    float2 f;
    asm("mov.b64 {%0,%1}, %2;" : "=f"(f.x), "=f"(f.y) : "l"(v));
    return f;
}

__device__ __forceinline__ float sigmoidf_(float x) {
    return __fdividef(1.0f, 1.0f + __expf(-x));
}
__device__ __forceinline__ float tanhf_(float x) {
    return 1.0f - __fdividef(2.0f, __expf(2.0f * x) + 1.0f);
}

// ---------------- cluster / DSMEM helpers ----------------
__device__ __forceinline__ uint32_t smem_u32(const void* p) {
    uint32_t a;
    asm("{ .reg .u64 t; cvta.to.shared.u64 t, %1; cvt.u32.u64 %0, t; }"
        : "=r"(a) : "l"(p));
    return a;
}
__device__ __forceinline__ uint32_t mapa_(uint32_t a, uint32_t rank) {
    uint32_t r;
    asm("mapa.shared::cluster.u32 %0, %1, %2;" : "=r"(r) : "r"(a), "r"(rank));
    return r;
}
__device__ __forceinline__ void st_cluster_u64(uint32_t addr,
                                               unsigned long long v) {
    asm volatile("st.shared::cluster.u64 [%0], %1;" ::"r"(addr), "l"(v)
                 : "memory");
}
__device__ __forceinline__ void st_release_cluster_s32(uint32_t addr, int v) {
    asm volatile("st.release.cluster.shared::cluster.b32 [%0], %1;" ::"r"(addr),
                 "r"(v)
                 : "memory");
}
__device__ __forceinline__ int ld_acquire_cluster_s32(uint32_t addr) {
    int v;
    asm volatile("ld.acquire.cluster.shared::cta.b32 %0, [%1];"
                 : "=r"(v) : "r"(addr) : "memory");
    return v;
}
// BOUNDED spin: fail-loud (proceed after ~100ms) instead of hanging the
// container. Never triggers when the protocol is correct.
__device__ __forceinline__ void spin_until_ge(uint32_t addr, int target) {
    if (ld_acquire_cluster_s32(addr) >= target) return;
    for (int it = 0; it < 2000000; it++) {
        if (ld_acquire_cluster_s32(addr) >= target) return;
        __nanosleep(32);
    }
}
__device__ __forceinline__ uint32_t ctarank_() {
    uint32_t r;
    asm("mov.u32 %0, %%cluster_ctarank;" : "=r"(r));
    return r;
}
#define CLUSTER_SYNC()                                                \
    do {                                                              \
        asm volatile("barrier.cluster.arrive.aligned;" ::: "memory"); \
        asm volatile("barrier.cluster.wait.aligned;" ::: "memory");   \
    } while (0)

// Partial dot over NC 16B chunks (4*NC MACs): xor-rotated SMEM broadcast
// reads against 2*NC packed matrix-column registers. 4 accumulator chains.
template <int NC>
__device__ __forceinline__ float dotx(const ulonglong2* hb, int baseChunk,
                                      int xv, const unsigned long long* cc) {
    unsigned long long a0 = 0, a1 = 0, a2 = 0, a3 = 0;
#pragma unroll
    for (int c = 0; c < NC; c += 2) {
        ulonglong2 v0 = hb[baseChunk + (c ^ xv)];
        ulonglong2 v1 = hb[baseChunk + ((c + 1) ^ xv)];
        a0 = ffma2(v0.x, cc[2 * c + 0], a0);
        a1 = ffma2(v0.y, cc[2 * c + 1], a1);
        a2 = ffma2(v1.x, cc[2 * c + 2], a2);
        a3 = ffma2(v1.y, cc[2 * c + 3], a3);
    }
    float2 f = up2(addx2(addx2(a0, a1), addx2(a2, a3)));
    return f.x + f.y;
}

// ---------------- GEMM: g_wx[M,128] = x[M,64] @ w0[64,128] ----------------
__global__ __launch_bounds__(128) void gemm_proj(const float* __restrict__ A,
                                                 const float* __restrict__ W) {
    constexpr int K = II;
    constexpr int KC = 32;
    __shared__ unsigned long long ATd[KC][66];
    __shared__ float Wsh[KC][HH];

    const int tid = threadIdx.x;
    const int row0 = blockIdx.x * 64;
    const int cp = tid & 63;
    const int rh = tid >> 6;

    unsigned long long acc[32];
#pragma unroll
    for (int i = 0; i < 32; i++) acc[i] = 0ULL;

    for (int k0 = 0; k0 < K; k0 += KC) {
#pragma unroll
        for (int i = 0; i < 16; i++) {
            int idx = tid + i * 128;
            int r = idx >> 5, k = idx & 31;
            float a = A[(size_t)(row0 + r) * K + (k0 + k)];
            ATd[k][r] = pk2(a, a);
        }
#pragma unroll
        for (int i = 0; i < 32; i++) {
            int idx = tid + i * 128;
            int k = idx >> 7, c = idx & 127;
            Wsh[k][c] = W[(size_t)(k0 + k) * HH + c];
        }
        __syncthreads();

#pragma unroll 4
        for (int k = 0; k < KC; k++) {
            float2 wv = *(const float2*)&Wsh[k][2 * cp];
            unsigned long long w2 = pk2(wv.x, wv.y);
            const unsigned long long* arow = &ATd[k][rh * 32];
#pragma unroll
            for (int rr = 0; rr < 16; rr++) {
                ulonglong2 av = *(const ulonglong2*)(arow + 2 * rr);
                acc[2 * rr] = ffma2(av.x, w2, acc[2 * rr]);
                acc[2 * rr + 1] = ffma2(av.y, w2, acc[2 * rr + 1]);
            }
        }
        __syncthreads();
    }

#pragma unroll
    for (int r = 0; r < 32; r++) {
        float2 v = up2(acc[r]);
        *(float2*)&g_wx[(size_t)(row0 + rh * 32 + r) * HH + 2 * cp] = v;
    }
}

// ---------------- 2-SM pipelined recurrence (cluster of 2) ----------------
// Cluster = (A: layer 0, B: layer 1+proj), one cluster per batch.
// 512 threads/CTA; thread: channel j = tid>>2, sub s = tid&3.
// A: quad K-split of u0 matvec (4 subs x 32 MACs).
// B: subs {0,1} = proj (w1.h0) halves, subs {2,3} = recur (u1.h1) halves,
//    each 64 MACs; shfl over the 4 subs yields proj+recur = full pre.
// A exports h0[t] into B's SMEM ring (depth 4) via DSMEM; per-lane
// release/acquire flags (inflag: A->B data ready; ack: B->A slot consumed).
__global__ __launch_bounds__(512, 1) __cluster_dims__(2, 1, 1)
void fused_cluster(
    const float* __restrict__ u0, const float* __restrict__ bg0,
    const float* __restrict__ bu0, const float* __restrict__ zeta0,
    const float* __restrict__ nu0, const float* __restrict__ lambd0,
    const float* __restrict__ gamma0, const float* __restrict__ w1,
    const float* __restrict__ u1, const float* __restrict__ bg1,
    const float* __restrict__ bu1, const float* __restrict__ zeta1,
    const float* __restrict__ nu1, const float* __restrict__ lambd1,
    const float* __restrict__ gamma1, float* __restrict__ out, int write_h) {
    __shared__ __align__(128) float ring[4][HH];  // B: h0 ring (A writes)
    __shared__ __align__(128) float hA[2][HH];    // A: own h0 ring
    __shared__ __align__(128) float h1B[2][HH];   // B: h1 ring
    __shared__ __align__(16) int inflag[32];      // B's: set by A (lane-wise)
    __shared__ __align__(16) int ack[32];         // A's: set by B (lane-wise)

    const int tid = threadIdx.x;
    const int j = tid >> 2;   // channel
    const int s = tid & 3;    // quad sub
    const int lane = tid & 31;
    const uint32_t rank = ctarank_();
    const int b = blockIdx.x >> 1;

    if (rank == 0) {
        // ================= A: layer 0 =================
        const int xv = 2 * s;          // rotations {0,2,4,6}: distinct mod 8
        const int baseChunk = 8 * s;   // k in [32s, 32s+32)
        unsigned long long cc[16];
#pragma unroll
        for (int c = 0; c < 8; c++) {
            int kk = 4 * (baseChunk + (c ^ xv));
            cc[2 * c] = pk2(u0[(size_t)kk * HH + j],
                            u0[(size_t)(kk + 1) * HH + j]);
            cc[2 * c + 1] = pk2(u0[(size_t)(kk + 2) * HH + j],
                                u0[(size_t)(kk + 3) * HH + j]);
        }
        float bgj = bg0[j], buj = bu0[j];
        float sz = sigmoidf_(zeta0[0]);
        float szn = sz + sigmoidf_(nu0[0]);
        float gcv = fminf(fmaxf(gamma0[0], 0.0f), 1.0f);
        float c1 = (1.0f - gcv) * lambd0[0];

        if (s == 0) hA[1][j] = 0.0f;
        if (tid < 32) ack[lane] = -1;
        __syncthreads();
        CLUSTER_SYNC();  // flags initialized in both CTAs

        const uint32_t rem_ring = mapa_(smem_u32(ring), 1);
        const uint32_t rem_flag = mapa_(smem_u32(inflag), 1);
        const uint32_t my_ack = smem_u32(ack) + 4 * lane;

        const float* __restrict__ wxp = g_wx + (size_t)b * SS * HH + j;
        float h_prev = 0.0f;
        float wx_cur = (s == 0) ? wxp[0] : 0.0f;

        for (int t = 0; t < SS; t++) {
            const ulonglong2* hb = (const ulonglong2*)hA[(t + 1) & 1];
            float part = dotx<8>(hb, baseChunk, xv, cc);
            part += __shfl_xor_sync(0xffffffffu, part, 1);
            part += __shfl_xor_sync(0xffffffffu, part, 2);
            if (s == 0) {
                int tn = (t + 1 < SS) ? (t + 1) : (SS - 1);
                float wx_nxt = wxp[(size_t)tn * HH];
                float pre = part + wx_cur;
                float z = sigmoidf_(pre + bgj);
                float hh = tanhf_(pre + buj);
                float coef = fmaf(-sz, z, szn);
                float h_new = fmaf(z, h_prev, coef * hh);
                float ho = fmaf(gcv, h_new, c1);
                hA[t & 1][j] = ho;
                h_prev = ho;
                wx_cur = wx_nxt;
            }
            __syncthreads();
            if (tid < 32) {
                // backpressure: B must have consumed slot content t-4
                spin_until_ge(my_ack, t - 4);
                ulonglong2 v = *((const ulonglong2*)hA[t & 1] + lane);
                uint32_t dst = rem_ring + (uint32_t)(t & 3) * 512u + lane * 16u;
                st_cluster_u64(dst, v.x);
                st_cluster_u64(dst + 8, v.y);
                st_release_cluster_s32(rem_flag + 4u * lane, t);
            }
        }
        if (write_h && s == 0)
            out[(size_t)BB * SS * HH + (size_t)b * HH + j] = h_prev;
        CLUSTER_SYNC();  // keep SMEM alive until B stops writing acks
    } else {
        // ================= B: layer 1 (+ proj) =================
        // subs 0,1: proj halves (16 chunks each) over ring h0;
        // subs 2,3: recur halves (16 chunks each) over h1B.
        // rotations {0,2,4,6}: 4 concurrent addresses in distinct bank quads.
        const int xv = 2 * s;
        const int baseChunk = 16 * (s & 1);  // chunks [16*(s&1), +16)
        const bool isProj = (s < 2);
        const float* __restrict__ Mx = isProj ? w1 : u1;
        unsigned long long cc[32];
#pragma unroll
        for (int c = 0; c < 16; c++) {
            int kk = 4 * (baseChunk + (c ^ xv));
            cc[2 * c] = pk2(Mx[(size_t)kk * HH + j],
                            Mx[(size_t)(kk + 1) * HH + j]);
            cc[2 * c + 1] = pk2(Mx[(size_t)(kk + 2) * HH + j],
                                Mx[(size_t)(kk + 3) * HH + j]);
        }
        float bgj = bg1[j], buj = bu1[j];
        float sz = sigmoidf_(zeta1[0]);
        float szn = sz + sigmoidf_(nu1[0]);
        float gcv = fminf(fmaxf(gamma1[0], 0.0f), 1.0f);
        float c1 = (1.0f - gcv) * lambd1[0];

        if (s == 0) h1B[1][j] = 0.0f;
        if (tid < 32) inflag[lane] = -1;
        __syncthreads();
        CLUSTER_SYNC();

        const uint32_t rem_ack = mapa_(smem_u32(ack), 0);
        const uint32_t my_flag = smem_u32(inflag) + 4 * lane;

        // prologue: slot 0 ready
        if (tid < 32) spin_until_ge(my_flag, 0);
        __syncthreads();

        float* __restrict__ outp = out + (size_t)b * SS * HH + j;
        float h_prev = 0.0f;

        for (int t = 0; t < SS; t++) {
            const ulonglong2* hb = isProj
                                       ? (const ulonglong2*)ring[t & 3]
                                       : (const ulonglong2*)h1B[(t + 1) & 1];
            float part = dotx<16>(hb, baseChunk, xv, cc);
            part += __shfl_xor_sync(0xffffffffu, part, 1);
            part += __shfl_xor_sync(0xffffffffu, part, 2);
            if (s == 0) {
                float pre = part;  // = proj (wx1[t]) + recur (u1.h1[t-1])
                float z = sigmoidf_(pre + bgj);
                float hh = tanhf_(pre + buj);
                float coef = fmaf(-sz, z, szn);
                float h_new = fmaf(z, h_prev, coef * hh);
                float ho = fmaf(gcv, h_new, c1);
                h1B[t & 1][j] = ho;
                *outp = ho;
                outp += HH;
                h_prev = ho;
            }
            if (tid < 32) {
                if (t + 1 < SS) spin_until_ge(my_flag, t + 1);
                if (t > 0) st_release_cluster_s32(rem_ack + 4u * lane, t - 1);
            }
            __syncthreads();
        }
        if (write_h && s == 0)
            out[(size_t)BB * SS * HH + (size_t)BB * HH + (size_t)b * HH + j] =
                h_prev;
        CLUSTER_SYNC();
    }
}

// ---------------- launch ----------------
extern "C" void kernel_launch(void* const* d_in, const int* in_sizes, int n_in,
                              void* d_out, int out_size) {
    const float* x      = (const float*)d_in[0];
    const float* w0     = (const float*)d_in[1];
    const float* u0     = (const float*)d_in[2];
    const float* bg0    = (const float*)d_in[3];
    const float* bu0    = (const float*)d_in[4];
    const float* zeta0  = (const float*)d_in[5];
    const float* nu0    = (const float*)d_in[6];
    const float* lambd0 = (const float*)d_in[7];
    const float* gamma0 = (const float*)d_in[8];
    const float* w1     = (const float*)d_in[9];
    const float* u1     = (const float*)d_in[10];
    const float* bg1    = (const float*)d_in[11];
    const float* bu1    = (const float*)d_in[12];
    const float* zeta1  = (const float*)d_in[13];
    const float* nu1    = (const float*)d_in[14];
    const float* lambd1 = (const float*)d_in[15];
    const float* gamma1 = (const float*)d_in[16];

    float* out = (float*)d_out;
    const int M = BB * SS;
    const int write_h = (out_size >= BB * SS * HH + 2 * BB * HH) ? 1 : 0;

    // wx0 = x @ w0
    gemm_proj<<<M / 64, 128>>>(x, w0);
    // 64 clusters x 2 CTAs: layer 0 on one SM, layer 1 (+proj) on its partner
    fused_cluster<<<2 * BB, 512>>>(u0, bg0, bu0, zeta0, nu0, lambd0, gamma0,
                                   w1, u1, bg1, bu1, zeta1, nu1, lambd1,
                                   gamma1, out, write_h);
}

// round 10
// speedup vs baseline: 1.4522x; 1.4522x over previous
#include <cuda_runtime.h>
#include <cuda_bf16.h>
#include <cstdint>

// Problem constants
#define BB 64
#define SS 2048
#define II 64
#define HH 128

// Scratch (allocation-free rule: __device__ globals)
__device__ float g_wx[BB * SS * HH];  // wx0 = x @ w0

// ---------------- f32x2 helpers ----------------
__device__ __forceinline__ unsigned long long pk2(float lo, float hi) {
    unsigned long long r;
    asm("mov.b64 %0, {%1,%2};" : "=l"(r) : "f"(lo), "f"(hi));
    return r;
}
__device__ __forceinline__ unsigned long long ffma2(unsigned long long a,
                                                    unsigned long long b,
                                                    unsigned long long c) {
    unsigned long long d;
    asm("fma.rn.f32x2 %0, %1, %2, %3;" : "=l"(d) : "l"(a), "l"(b), "l"(c));
    return d;
}
__device__ __forceinline__ unsigned long long addx2(unsigned long long a,
                                                    unsigned long long b) {
    unsigned long long d;
    asm("add.rn.f32x2 %0, %1, %2;" : "=l"(d) : "l"(a), "l"(b));
    return d;
}
__device__ __forceinline__ float2 up2(unsigned long long v) {
    float2 f;
    asm("mov.b64 {%0,%1}, %2;" : "=f"(f.x), "=f"(f.y) : "l"(v));
    return f;
}

__device__ __forceinline__ float sigmoidf_(float x) {
    return __fdividef(1.0f, 1.0f + __expf(-x));
}
__device__ __forceinline__ float tanhf_(float x) {
    return 1.0f - __fdividef(2.0f, __expf(2.0f * x) + 1.0f);
}

// ---------------- GEMM: g_wx[M,128] = x[M,64] @ w0[64,128] ----------------
__global__ __launch_bounds__(128) void gemm_proj(const float* __restrict__ A,
                                                 const float* __restrict__ W) {
    constexpr int K = II;
    constexpr int KC = 32;
    __shared__ unsigned long long ATd[KC][66];
    __shared__ float Wsh[KC][HH];

    const int tid = threadIdx.x;
    const int row0 = blockIdx.x * 64;
    const int cp = tid & 63;
    const int rh = tid >> 6;

    unsigned long long acc[32];
#pragma unroll
    for (int i = 0; i < 32; i++) acc[i] = 0ULL;

    for (int k0 = 0; k0 < K; k0 += KC) {
#pragma unroll
        for (int i = 0; i < 16; i++) {
            int idx = tid + i * 128;
            int r = idx >> 5, k = idx & 31;
            float a = A[(size_t)(row0 + r) * K + (k0 + k)];
            ATd[k][r] = pk2(a, a);
        }
#pragma unroll
        for (int i = 0; i < 32; i++) {
            int idx = tid + i * 128;
            int k = idx >> 7, c = idx & 127;
            Wsh[k][c] = W[(size_t)(k0 + k) * HH + c];
        }
        __syncthreads();

#pragma unroll 4
        for (int k = 0; k < KC; k++) {
            float2 wv = *(const float2*)&Wsh[k][2 * cp];
            unsigned long long w2 = pk2(wv.x, wv.y);
            const unsigned long long* arow = &ATd[k][rh * 32];
#pragma unroll
            for (int rr = 0; rr < 16; rr++) {
                ulonglong2 av = *(const ulonglong2*)(arow + 2 * rr);
                acc[2 * rr] = ffma2(av.x, w2, acc[2 * rr]);
                acc[2 * rr + 1] = ffma2(av.y, w2, acc[2 * rr + 1]);
            }
        }
        __syncthreads();
    }

#pragma unroll
    for (int r = 0; r < 32; r++) {
        float2 v = up2(acc[r]);
        *(float2*)&g_wx[(size_t)(row0 + rh * 32 + r) * HH + 2 * cp] = v;
    }
}

// Outer-product quad dot: lane covers 4 channels x 32 K-values.
// Each 16B h chunk is loaded ONCE and reused for 4 channels (8 ffma2) --
// 4x less SMEM crossbar traffic than channel-per-thread layouts.
// Returns the lane's OWN channel sum (channel 4g+p), reduced over the 4
// K-parts via shfl.xor(8),(16).
__device__ __forceinline__ float dotq(const float* hbf, int p, int rp,
                                      const unsigned long long* cc) {
    const ulonglong2* hb = (const ulonglong2*)hbf + 8 * p;
    unsigned long long a0 = 0, a1 = 0, a2 = 0, a3 = 0, a4 = 0, a5 = 0, a6 = 0,
                       a7 = 0;
#pragma unroll
    for (int ci = 0; ci < 8; ci++) {
        ulonglong2 v = hb[ci ^ rp];
        a0 = ffma2(v.x, cc[0 * 16 + ci * 2 + 0], a0);
        a1 = ffma2(v.y, cc[0 * 16 + ci * 2 + 1], a1);
        a2 = ffma2(v.x, cc[1 * 16 + ci * 2 + 0], a2);
        a3 = ffma2(v.y, cc[1 * 16 + ci * 2 + 1], a3);
        a4 = ffma2(v.x, cc[2 * 16 + ci * 2 + 0], a4);
        a5 = ffma2(v.y, cc[2 * 16 + ci * 2 + 1], a5);
        a6 = ffma2(v.x, cc[3 * 16 + ci * 2 + 0], a6);
        a7 = ffma2(v.y, cc[3 * 16 + ci * 2 + 1], a7);
    }
    float2 f0 = up2(addx2(a0, a1));
    float2 f1 = up2(addx2(a2, a3));
    float2 f2 = up2(addx2(a4, a5));
    float2 f3 = up2(addx2(a6, a7));
    float s0 = f0.x + f0.y;
    float s1 = f1.x + f1.y;
    float s2 = f2.x + f2.y;
    float s3 = f3.x + f3.y;
    s0 += __shfl_xor_sync(0xffffffffu, s0, 8);
    s1 += __shfl_xor_sync(0xffffffffu, s1, 8);
    s2 += __shfl_xor_sync(0xffffffffu, s2, 8);
    s3 += __shfl_xor_sync(0xffffffffu, s3, 8);
    s0 += __shfl_xor_sync(0xffffffffu, s0, 16);
    s1 += __shfl_xor_sync(0xffffffffu, s1, 16);
    s2 += __shfl_xor_sync(0xffffffffu, s2, 16);
    s3 += __shfl_xor_sync(0xffffffffu, s3, 16);
    return (p == 0) ? s0 : (p == 1) ? s1 : (p == 2) ? s2 : s3;
}

// ---------------- Fused 2-layer pipelined recurrence ----------------
// One CTA per batch, 384 threads = 12 warps = 3 roles x 4 warps:
//   role 0 (warps 0-3):  layer-0 step i
//   role 1 (warps 4-7):  wx1[i-1] = h0[i-1]@w1
//   role 2 (warps 8-11): layer-1 step t=i-2
// Lane layout: p = lane>>3 (K-part, 32 K-values), g = lane&7 (channel group);
// lane's 4 channels = 32*warpInRole + 4g + {0..3}; own channel = +p.
// K-part chunk order is XOR-rotated by 2p so the 4 concurrent 16B broadcast
// lines occupy distinct bank quads.
__global__ __launch_bounds__(384) void fused_recurrence(
    const float* __restrict__ u0, const float* __restrict__ bg0,
    const float* __restrict__ bu0, const float* __restrict__ zeta0,
    const float* __restrict__ nu0, const float* __restrict__ lambd0,
    const float* __restrict__ gamma0, const float* __restrict__ w1,
    const float* __restrict__ u1, const float* __restrict__ bg1,
    const float* __restrict__ bu1, const float* __restrict__ zeta1,
    const float* __restrict__ nu1, const float* __restrict__ lambd1,
    const float* __restrict__ gamma1, float* __restrict__ out, int write_h) {
    const int b = blockIdx.x;
    const int tid = threadIdx.x;
    const int wid = tid >> 5;
    const int role = wid >> 2;  // 0,1,2
    const int wq = wid & 3;     // warp-in-role
    const int lane = tid & 31;
    const int p = lane >> 3;    // K-part
    const int g = lane & 7;     // channel group
    const int chBase = wq * 32 + g * 4;
    const int ch = chBase + p;  // own channel
    const int rp = 2 * p;       // chunk rotation

    __shared__ __align__(16) float h0_sh[2][HH];
    __shared__ __align__(16) float wx1_sh[2][HH];
    __shared__ __align__(16) float h1_sh[2][HH];

    // Matrix block: 4 channels x 32 K-values in 64 packed f32x2 registers,
    // stored in the rotated chunk order used by dotq.
    const float* __restrict__ M = (role == 0) ? u0 : (role == 1) ? w1 : u1;
    unsigned long long cc[64];
#pragma unroll
    for (int cix = 0; cix < 4; cix++) {
#pragma unroll
        for (int ci = 0; ci < 8; ci++) {
            int k = 4 * (8 * p + (ci ^ rp));
            int col = chBase + cix;
            cc[cix * 16 + ci * 2 + 0] =
                pk2(M[(size_t)k * HH + col], M[(size_t)(k + 1) * HH + col]);
            cc[cix * 16 + ci * 2 + 1] =
                pk2(M[(size_t)(k + 2) * HH + col], M[(size_t)(k + 3) * HH + col]);
        }
    }

    // Per-role scalars (for own channel)
    float bgj = 0.f, buj = 0.f, szn = 0.f, sz = 0.f, gcv = 0.f, c1 = 0.f;
    if (role == 0) {
        bgj = bg0[ch]; buj = bu0[ch];
        sz = sigmoidf_(zeta0[0]);
        szn = sz + sigmoidf_(nu0[0]);
        gcv = fminf(fmaxf(gamma0[0], 0.0f), 1.0f);
        c1 = (1.0f - gcv) * lambd0[0];
    } else if (role == 2) {
        bgj = bg1[ch]; buj = bu1[ch];
        sz = sigmoidf_(zeta1[0]);
        szn = sz + sigmoidf_(nu1[0]);
        gcv = fminf(fmaxf(gamma1[0], 0.0f), 1.0f);
        c1 = (1.0f - gcv) * lambd1[0];
    }

    if (role == 0) h0_sh[1][ch] = 0.0f;
    if (role == 2) h1_sh[1][ch] = 0.0f;

    float h_prev = 0.0f;  // own-channel previous h (role0: h0, role2: h1)

    const float* __restrict__ wxp = g_wx + (size_t)b * SS * HH + ch;
    float* __restrict__ outp = out + (size_t)b * SS * HH + ch;

    __syncthreads();
    float wx_cur = (role == 0) ? wxp[0] : 0.0f;

    for (int i = 0; i < SS + 2; i++) {
        if (role == 0) {
            if (i < SS) {
                int tn = (i + 1 < SS) ? (i + 1) : (SS - 1);
                float wx_nxt = wxp[(size_t)tn * HH];
                float pre = dotq(h0_sh[(i + 1) & 1], p, rp, cc) + wx_cur;
                float z = sigmoidf_(pre + bgj);
                float hh = tanhf_(pre + buj);
                float coef = fmaf(-sz, z, szn);
                float h_new = fmaf(z, h_prev, coef * hh);
                float ho = fmaf(gcv, h_new, c1);
                h0_sh[i & 1][ch] = ho;
                h_prev = ho;
                wx_cur = wx_nxt;
            }
        } else if (role == 1) {
            if (i >= 1 && i <= SS) {
                wx1_sh[(i - 1) & 1][ch] = dotq(h0_sh[(i - 1) & 1], p, rp, cc);
            }
        } else {
            if (i >= 2) {
                int t = i - 2;
                float pre = dotq(h1_sh[(t + 1) & 1], p, rp, cc) +
                            wx1_sh[t & 1][ch];
                float z = sigmoidf_(pre + bgj);
                float hh = tanhf_(pre + buj);
                float coef = fmaf(-sz, z, szn);
                float h_new = fmaf(z, h_prev, coef * hh);
                float ho = fmaf(gcv, h_new, c1);
                h1_sh[t & 1][ch] = ho;
                outp[(size_t)t * HH] = ho;
                h_prev = ho;
            }
        }
        __syncthreads();
    }

    if (write_h) {
        if (role == 0)
            out[(size_t)BB * SS * HH + (size_t)b * HH + ch] = h_prev;  // h0T
        else if (role == 2)
            out[(size_t)BB * SS * HH + (size_t)BB * HH + (size_t)b * HH + ch] =
                h_prev;  // h1T
    }
}

// ---------------- launch ----------------
extern "C" void kernel_launch(void* const* d_in, const int* in_sizes, int n_in,
                              void* d_out, int out_size) {
    const float* x      = (const float*)d_in[0];
    const float* w0     = (const float*)d_in[1];
    const float* u0     = (const float*)d_in[2];
    const float* bg0    = (const float*)d_in[3];
    const float* bu0    = (const float*)d_in[4];
    const float* zeta0  = (const float*)d_in[5];
    const float* nu0    = (const float*)d_in[6];
    const float* lambd0 = (const float*)d_in[7];
    const float* gamma0 = (const float*)d_in[8];
    const float* w1     = (const float*)d_in[9];
    const float* u1     = (const float*)d_in[10];
    const float* bg1    = (const float*)d_in[11];
    const float* bu1    = (const float*)d_in[12];
    const float* zeta1  = (const float*)d_in[13];
    const float* nu1    = (const float*)d_in[14];
    const float* lambd1 = (const float*)d_in[15];
    const float* gamma1 = (const float*)d_in[16];

    float* out = (float*)d_out;
    const int M = BB * SS;
    const int write_h = (out_size >= BB * SS * HH + 2 * BB * HH) ? 1 : 0;

    // wx0 = x @ w0
    gemm_proj<<<M / 64, 128>>>(x, w0);
    // fused: layer0 + (out0 @ w1) + layer1, outer-product operand reuse
    fused_recurrence<<<BB, 384>>>(u0, bg0, bu0, zeta0, nu0, lambd0, gamma0, w1,
                                  u1, bg1, bu1, zeta1, nu1, lambd1, gamma1, out,
                                  write_h);
}